// round 4
// baseline (speedup 1.0000x reference)
#include <cuda_runtime.h>
#include <math.h>

// Problem dims
#define Bb 16
#define Ss 512
#define Dd 768
#define Hh 12
#define FF 3072
#define Ll 6
#define HD 64
#define BH (Bb*Hh)      // 192
#define NROWS (Bb*Ss)   // 8192

// ---------------- scratch (device globals; no runtime allocation) ----------------
__device__ float g_x  [NROWS*Dd];
__device__ float g_tmp[NROWS*Dd];
__device__ float g_q  [NROWS*Dd];
__device__ float g_k  [NROWS*Dd];
__device__ float g_v  [NROWS*Dd];
__device__ float g_ctx[NROWS*Dd];
__device__ float g_ff [NROWS*FF];
__device__ float g_sc [(size_t)BH*Ss*Ss];

// ---------------- embedding segment-merge + pos add ----------------
// segment_ids rows are sorted -> each output segment is a contiguous run.
__global__ void merge_kernel(const int* __restrict__ ids, const int* __restrict__ seg,
                             const float* __restrict__ emb, const float* __restrict__ pos,
                             float* __restrict__ out)
{
    int s = blockIdx.x, b = blockIdx.y;
    const int* sr = seg + b*Ss;
    int lo = 0, hi = Ss;
    while (lo < hi) { int m = (lo+hi)>>1; if (sr[m] <  s) lo = m+1; else hi = m; }
    int st = lo;
    lo = st; hi = Ss;
    while (lo < hi) { int m = (lo+hi)>>1; if (sr[m] <= s) lo = m+1; else hi = m; }
    int en = lo;
    const int* idr = ids + b*Ss;
    for (int d = threadIdx.x; d < Dd; d += blockDim.x) {
        float a;
        if (st == en) {
            a = emb[d];                                   // pad = emb_table[0]
        } else {
            a = 0.f;
            for (int i = st; i < en; i++)
                a += emb[(size_t)idr[i]*Dd + d];
        }
        out[((size_t)b*Ss + s)*Dd + d] = a + pos[s*Dd + d];
    }
}

// ---------------- LayerNorm (optionally with residual), 1 block / row ----------------
__global__ void ln_kernel(const float* __restrict__ in, const float* __restrict__ res,
                          float* __restrict__ out, const float* __restrict__ gamma,
                          const float* __restrict__ beta)
{
    __shared__ float red[256];
    int row = blockIdx.x;
    const float* ip = in + (size_t)row*Dd;
    const float* rp = res ? res + (size_t)row*Dd : nullptr;
    int t = threadIdx.x;
    float v[3];
    float s = 0.f;
#pragma unroll
    for (int i = 0; i < 3; i++) {
        int d = t + i*256;
        v[i] = ip[d] + (rp ? rp[d] : 0.f);
        s += v[i];
    }
    red[t] = s; __syncthreads();
    for (int o = 128; o > 0; o >>= 1) { if (t < o) red[t] += red[t+o]; __syncthreads(); }
    float mean = red[0] * (1.f/Dd);
    __syncthreads();
    float s2 = 0.f;
#pragma unroll
    for (int i = 0; i < 3; i++) { float dd = v[i]-mean; s2 += dd*dd; }
    red[t] = s2; __syncthreads();
    for (int o = 128; o > 0; o >>= 1) { if (t < o) red[t] += red[t+o]; __syncthreads(); }
    float inv = rsqrtf(red[0]*(1.f/Dd) + 1e-12f);
#pragma unroll
    for (int i = 0; i < 3; i++) {
        int d = t + i*256;
        out[(size_t)row*Dd + d] = (v[i]-mean)*inv*gamma[d] + beta[d];
    }
}

// ---------------- generic SGEMM: C[M,N] = act(A[M,K] @ B[K,N] + bias) ----------------
// 64x64 block tile, K-tile 16, 256 threads, 4x4 micro-tile. Dims assumed multiples of 64/16.
__global__ void gemm_bias(const float* __restrict__ A, const float* __restrict__ B,
                          const float* __restrict__ bias, float* __restrict__ C,
                          int M, int N, int K, int act)
{
    __shared__ float As[16][68];   // [k][m], padded (16B-aligned rows, ~2-way store conflict)
    __shared__ float Bs[16][64];   // [k][n]
    const int t = threadIdx.x;
    const int tx = t & 15, ty = t >> 4;
    const int bm = blockIdx.y * 64;
    const int bn = blockIdx.x * 64;
    float acc[4][4] = {};
    for (int k0 = 0; k0 < K; k0 += 16) {
#pragma unroll
        for (int i = 0; i < 4; i++) {
            int idx = t + i*256;
            int r  = idx >> 4, c  = idx & 15;   // A tile 64x16
            As[c][r]  = A[(size_t)(bm + r)*K + k0 + c];
            int r2 = idx >> 6, c2 = idx & 63;   // B tile 16x64
            Bs[r2][c2] = B[(size_t)(k0 + r2)*N + bn + c2];
        }
        __syncthreads();
#pragma unroll
        for (int kk = 0; kk < 16; kk++) {
            float4 a4 = *reinterpret_cast<const float4*>(&As[kk][ty*4]);
            float4 b4 = *reinterpret_cast<const float4*>(&Bs[kk][tx*4]);
            float a[4] = {a4.x, a4.y, a4.z, a4.w};
            float b[4] = {b4.x, b4.y, b4.z, b4.w};
#pragma unroll
            for (int i = 0; i < 4; i++)
#pragma unroll
                for (int j = 0; j < 4; j++)
                    acc[i][j] = fmaf(a[i], b[j], acc[i][j]);
        }
        __syncthreads();
    }
#pragma unroll
    for (int i = 0; i < 4; i++) {
        size_t row = bm + ty*4 + i;
#pragma unroll
        for (int j = 0; j < 4; j++) {
            float vv = acc[i][j] + bias[bn + tx*4 + j];
            if (act == 1) vv = 0.5f*vv*(1.0f + erff(vv*0.70710678118654752f));  // exact GELU
            C[row*N + bn + tx*4 + j] = vv;
        }
    }
}

// ---------------- attention scores: sc[z, q, k] = (q . k)/8 ; 64x64 tile / block ----------------
__global__ void attn_scores(const float* __restrict__ q, const float* __restrict__ k,
                            float* __restrict__ sc)
{
    __shared__ float Qs[64][65];
    __shared__ float Ks[64][65];
    int kt = blockIdx.x, qt = blockIdx.y, z = blockIdx.z;
    int b = z / Hh, h = z % Hh;
    const float* qb = q + ((size_t)b*Ss)*Dd + h*HD;
    const float* kb = k + ((size_t)b*Ss)*Dd + h*HD;
    int t = threadIdx.x;
#pragma unroll
    for (int i = 0; i < 16; i++) {
        int idx = t + i*256;
        int r = idx >> 6, c = idx & 63;
        Qs[r][c] = qb[(size_t)(qt*64 + r)*Dd + c];
        Ks[r][c] = kb[(size_t)(kt*64 + r)*Dd + c];
    }
    __syncthreads();
    int tx = t & 15, ty = t >> 4;
    float acc[4][4] = {};
#pragma unroll 4
    for (int kk = 0; kk < 64; kk++) {
        float a[4], bb[4];
#pragma unroll
        for (int i = 0; i < 4; i++) { a[i] = Qs[ty*4+i][kk]; bb[i] = Ks[tx*4+i][kk]; }
#pragma unroll
        for (int i = 0; i < 4; i++)
#pragma unroll
            for (int j = 0; j < 4; j++)
                acc[i][j] = fmaf(a[i], bb[j], acc[i][j]);
    }
    float* outp = sc + (size_t)z*Ss*Ss;
#pragma unroll
    for (int i = 0; i < 4; i++) {
        size_t row = qt*64 + ty*4 + i;
#pragma unroll
        for (int j = 0; j < 4; j++)
            outp[row*Ss + kt*64 + tx*4 + j] = acc[i][j]*0.125f;
    }
}

// ---------------- row softmax with key mask bias, 1 block / row ----------------
__global__ void softmax_kernel(float* __restrict__ sc, const int* __restrict__ mask)
{
    __shared__ float red[256];
    size_t row = blockIdx.x;
    int z = blockIdx.x >> 9;               // bh index
    int b = z / Hh;
    float* rp = sc + row*Ss;
    int t = threadIdx.x;
    float v0 = rp[t]     + (mask[b*Ss + t]       ? 0.f : -1e9f);
    float v1 = rp[t+256] + (mask[b*Ss + t + 256] ? 0.f : -1e9f);
    float m = fmaxf(v0, v1);
    red[t] = m; __syncthreads();
    for (int o = 128; o > 0; o >>= 1) { if (t < o) red[t] = fmaxf(red[t], red[t+o]); __syncthreads(); }
    m = red[0]; __syncthreads();
    float e0 = __expf(v0 - m), e1 = __expf(v1 - m);
    red[t] = e0 + e1; __syncthreads();
    for (int o = 128; o > 0; o >>= 1) { if (t < o) red[t] += red[t+o]; __syncthreads(); }
    float inv = 1.f/red[0];
    rp[t] = e0*inv; rp[t+256] = e1*inv;
}

// ---------------- ctx = A @ V per head: 32 q-rows x 64 cols / block ----------------
__global__ void attn_ctx(const float* __restrict__ sc, const float* __restrict__ v,
                         float* __restrict__ ctx)
{
    __shared__ float As[32][65];
    __shared__ float Vs[64][64];
    int qt = blockIdx.x, z = blockIdx.y;
    int b = z / Hh, h = z % Hh;
    const float* ap = sc + (size_t)z*Ss*Ss;
    const float* vb = v + ((size_t)b*Ss)*Dd + h*HD;
    int t = threadIdx.x;
    int r = t >> 3, cg = t & 7;
    float acc[8] = {};
    for (int k0 = 0; k0 < Ss; k0 += 64) {
#pragma unroll
        for (int i = 0; i < 8; i++) {             // A tile 32x64
            int idx = t + i*256;
            int rr = idx >> 6, cc = idx & 63;
            As[rr][cc] = ap[(size_t)(qt*32 + rr)*Ss + k0 + cc];
        }
#pragma unroll
        for (int i = 0; i < 16; i++) {            // V tile 64x64
            int idx = t + i*256;
            int rr = idx >> 6, cc = idx & 63;
            Vs[rr][cc] = vb[(size_t)(k0 + rr)*Dd + cc];
        }
        __syncthreads();
#pragma unroll 8
        for (int kk = 0; kk < 64; kk++) {
            float a = As[r][kk];
            const float4* vp = reinterpret_cast<const float4*>(&Vs[kk][cg*8]);
            float4 x0 = vp[0], x1 = vp[1];
            acc[0] = fmaf(a, x0.x, acc[0]); acc[1] = fmaf(a, x0.y, acc[1]);
            acc[2] = fmaf(a, x0.z, acc[2]); acc[3] = fmaf(a, x0.w, acc[3]);
            acc[4] = fmaf(a, x1.x, acc[4]); acc[5] = fmaf(a, x1.y, acc[5]);
            acc[6] = fmaf(a, x1.z, acc[6]); acc[7] = fmaf(a, x1.w, acc[7]);
        }
        __syncthreads();
    }
    size_t orow = (size_t)b*Ss + qt*32 + r;
#pragma unroll
    for (int j = 0; j < 8; j++)
        ctx[orow*Dd + h*HD + cg*8 + j] = acc[j];
}

// ---------------- head: logits = relu(x[:,0] @ preW + preB) @ clsW + clsB ----------------
__global__ void head_kernel(const float* __restrict__ x, const float* __restrict__ preW,
                            const float* __restrict__ preB, const float* __restrict__ clsW,
                            const float* __restrict__ clsB, float* __restrict__ out)
{
    __shared__ float xr[Dd];
    __shared__ float pre[Dd];
    int b = blockIdx.x, t = threadIdx.x;
    for (int d = t; d < Dd; d += 256) xr[d] = x[((size_t)b*Ss)*Dd + d];
    __syncthreads();
    for (int o = t; o < Dd; o += 256) {
        float a = preB[o];
        for (int kk = 0; kk < Dd; kk++) a = fmaf(xr[kk], preW[(size_t)kk*Dd + o], a);
        pre[o] = fmaxf(a, 0.f);
    }
    __syncthreads();
    if (t < 3) {
        float a = clsB[t];
        for (int kk = 0; kk < Dd; kk++) a = fmaf(pre[kk], clsW[kk*3 + t], a);
        out[b*3 + t] = a;
    }
}

// ---------------- host launcher ----------------
extern "C" void kernel_launch(void* const* d_in, const int* in_sizes, int n_in,
                              void* d_out, int out_size)
{
    const int*   input_ids = (const int*)d_in[0];
    const int*   seg_ids   = (const int*)d_in[1];
    const int*   attn_mask = (const int*)d_in[2];
    // d_in[3] = label_ids (unused)
    const float* emb_table = (const float*)d_in[4];
    const float* pos_emb   = (const float*)d_in[5];
    const float* emb_ln_s  = (const float*)d_in[6];
    const float* emb_ln_b  = (const float*)d_in[7];
    const float* Wq = (const float*)d_in[8];
    const float* bq = (const float*)d_in[9];
    const float* Wk = (const float*)d_in[10];
    const float* bk = (const float*)d_in[11];
    const float* Wv = (const float*)d_in[12];
    const float* bv = (const float*)d_in[13];
    const float* Wo = (const float*)d_in[14];
    const float* bo = (const float*)d_in[15];
    const float* ln1_s = (const float*)d_in[16];
    const float* ln1_b = (const float*)d_in[17];
    const float* W1 = (const float*)d_in[18];
    const float* b1 = (const float*)d_in[19];
    const float* W2 = (const float*)d_in[20];
    const float* b2 = (const float*)d_in[21];
    const float* ln2_s = (const float*)d_in[22];
    const float* ln2_b = (const float*)d_in[23];
    const float* pre_W = (const float*)d_in[24];
    const float* pre_b = (const float*)d_in[25];
    const float* cls_W = (const float*)d_in[26];
    const float* cls_b = (const float*)d_in[27];
    float* logits = (float*)d_out;

    float *x, *tmp, *q, *k, *v, *ctx, *ff, *sc;
    cudaGetSymbolAddress((void**)&x,   g_x);
    cudaGetSymbolAddress((void**)&tmp, g_tmp);
    cudaGetSymbolAddress((void**)&q,   g_q);
    cudaGetSymbolAddress((void**)&k,   g_k);
    cudaGetSymbolAddress((void**)&v,   g_v);
    cudaGetSymbolAddress((void**)&ctx, g_ctx);
    cudaGetSymbolAddress((void**)&ff,  g_ff);
    cudaGetSymbolAddress((void**)&sc,  g_sc);

    // embedding merge + pos, then LN -> x
    merge_kernel<<<dim3(Ss, Bb), 128>>>(input_ids, seg_ids, emb_table, pos_emb, tmp);
    ln_kernel<<<NROWS, 256>>>(tmp, nullptr, x, emb_ln_s, emb_ln_b);

    dim3 gP(Dd/64, NROWS/64);    // 12 x 128  (N=768 projections)
    dim3 gF1(FF/64, NROWS/64);   // 48 x 128  (N=3072)

    for (int l = 0; l < Ll; l++) {
        const float* wq = Wq + (size_t)l*Dd*Dd;
        const float* wk = Wk + (size_t)l*Dd*Dd;
        const float* wv = Wv + (size_t)l*Dd*Dd;
        const float* wo = Wo + (size_t)l*Dd*Dd;
        const float* w1 = W1 + (size_t)l*Dd*FF;
        const float* w2 = W2 + (size_t)l*FF*Dd;

        gemm_bias<<<gP, 256>>>(x, wq, bq + l*Dd, q, NROWS, Dd, Dd, 0);
        gemm_bias<<<gP, 256>>>(x, wk, bk + l*Dd, k, NROWS, Dd, Dd, 0);
        gemm_bias<<<gP, 256>>>(x, wv, bv + l*Dd, v, NROWS, Dd, Dd, 0);

        attn_scores<<<dim3(Ss/64, Ss/64, BH), 256>>>(q, k, sc);
        softmax_kernel<<<BH*Ss, 256>>>(sc, attn_mask);
        attn_ctx<<<dim3(Ss/32, BH), 256>>>(sc, v, ctx);

        gemm_bias<<<gP, 256>>>(ctx, wo, bo + l*Dd, tmp, NROWS, Dd, Dd, 0);
        ln_kernel<<<NROWS, 256>>>(x, tmp, x, ln1_s + l*Dd, ln1_b + l*Dd);

        gemm_bias<<<gF1, 256>>>(x, w1, b1 + l*FF, ff, NROWS, FF, Dd, 1);     // + exact GELU
        gemm_bias<<<gP, 256>>>(ff, w2, b2 + l*Dd, tmp, NROWS, Dd, FF, 0);
        ln_kernel<<<NROWS, 256>>>(x, tmp, x, ln2_s + l*Dd, ln2_b + l*Dd);
    }

    head_kernel<<<Bb, 256>>>(x, pre_W, pre_b, cls_W, cls_b, logits);
}

// round 8
// speedup vs baseline: 1.8291x; 1.8291x over previous
#include <cuda_runtime.h>
#include <cuda_bf16.h>
#include <cstdint>
#include <math.h>

// Problem dims
#define Bb 16
#define Ss 512
#define Dd 768
#define Hh 12
#define FF 3072
#define Ll 6
#define HD 64
#define BH (Bb*Hh)
#define NROWS (Bb*Ss)

// ---------------- scratch (device globals; no runtime allocation) ----------------
__device__ float g_x  [NROWS*Dd];
__device__ float g_tmp[NROWS*Dd];
__device__ float g_q  [NROWS*Dd];
__device__ float g_k  [NROWS*Dd];
__device__ float g_v  [NROWS*Dd];
__device__ float g_ctx[NROWS*Dd];
__device__ float g_ff [NROWS*FF];
__device__ float g_sc [(size_t)BH*Ss*Ss];

// ---------------- embedding segment-merge + pos add ----------------
__global__ void merge_kernel(const int* __restrict__ ids, const int* __restrict__ seg,
                             const float* __restrict__ emb, const float* __restrict__ pos,
                             float* __restrict__ out)
{
    int s = blockIdx.x;
    int b = blockIdx.y;
    const int* sr = seg + b*Ss;
    int lo = 0;
    int hi = Ss;
    while (lo < hi) {
        int m = (lo + hi) >> 1;
        if (sr[m] < s) lo = m + 1; else hi = m;
    }
    int st = lo;
    lo = st;
    hi = Ss;
    while (lo < hi) {
        int m = (lo + hi) >> 1;
        if (sr[m] <= s) lo = m + 1; else hi = m;
    }
    int en = lo;
    const int* idr = ids + b*Ss;
    for (int d = threadIdx.x; d < Dd; d += blockDim.x) {
        float a;
        if (st == en) {
            a = emb[d];
        } else {
            a = 0.0f;
            for (int i = st; i < en; i++) {
                a += emb[(size_t)idr[i]*Dd + d];
            }
        }
        out[((size_t)b*Ss + s)*Dd + d] = a + pos[s*Dd + d];
    }
}

// ---------------- LayerNorm (optionally with residual), 1 block / row ----------------
__global__ void ln_kernel(const float* __restrict__ in, const float* __restrict__ res,
                          float* __restrict__ out, const float* __restrict__ gamma,
                          const float* __restrict__ beta)
{
    __shared__ float red[256];
    int row = blockIdx.x;
    const float* ip = in + (size_t)row*Dd;
    const float* rp = (res != nullptr) ? (res + (size_t)row*Dd) : nullptr;
    int t = threadIdx.x;
    float v0 = ip[t];
    float v1 = ip[t + 256];
    float v2 = ip[t + 512];
    if (rp != nullptr) {
        v0 += rp[t];
        v1 += rp[t + 256];
        v2 += rp[t + 512];
    }
    red[t] = v0 + v1 + v2;
    __syncthreads();
    for (int o = 128; o > 0; o >>= 1) {
        if (t < o) red[t] += red[t + o];
        __syncthreads();
    }
    float mean = red[0] * (1.0f / Dd);
    __syncthreads();
    float d0 = v0 - mean;
    float d1 = v1 - mean;
    float d2 = v2 - mean;
    red[t] = d0*d0 + d1*d1 + d2*d2;
    __syncthreads();
    for (int o = 128; o > 0; o >>= 1) {
        if (t < o) red[t] += red[t + o];
        __syncthreads();
    }
    float inv = rsqrtf(red[0] * (1.0f / Dd) + 1e-12f);
    out[(size_t)row*Dd + t]       = d0*inv*gamma[t]       + beta[t];
    out[(size_t)row*Dd + t + 256] = d1*inv*gamma[t + 256] + beta[t + 256];
    out[(size_t)row*Dd + t + 512] = d2*inv*gamma[t + 512] + beta[t + 512];
}

// ---------------- tensor-core GEMM with bf16x3 split precision ----------------
// C[M,N] = act(A[M,K] @ B[K,N] + bias).  A,B,C fp32 in gmem.
// A = Ah + Al (bf16 pair), B = Bh + Bl.  acc += Ah*Bh + Ah*Bl + Al*Bh (fp32 accum).
// Block tile 128x128, K-tile 32, 256 threads (8 warps as 4m x 2n), warp tile 32x64.

#define ASTRIDE 40
#define BSTRIDE 136

union BF16x4 {
    __nv_bfloat16 b[4];
    uint2 u;
};

__device__ __forceinline__ void ldsm4(uint32_t* r, uint32_t addr)
{
    asm volatile("ldmatrix.sync.aligned.m8n8.x4.shared.b16 {%0,%1,%2,%3}, [%4];"
        : "=r"(r[0]), "=r"(r[1]), "=r"(r[2]), "=r"(r[3]) : "r"(addr));
}

__device__ __forceinline__ void ldsm4t(uint32_t* r, uint32_t addr)
{
    asm volatile("ldmatrix.sync.aligned.m8n8.x4.trans.shared.b16 {%0,%1,%2,%3}, [%4];"
        : "=r"(r[0]), "=r"(r[1]), "=r"(r[2]), "=r"(r[3]) : "r"(addr));
}

__device__ __forceinline__ void mma16816(float* c, const uint32_t* a, const uint32_t* b)
{
    asm volatile("mma.sync.aligned.m16n8k16.row.col.f32.bf16.bf16.f32 "
        "{%0,%1,%2,%3}, {%4,%5,%6,%7}, {%8,%9}, {%0,%1,%2,%3};"
        : "+f"(c[0]), "+f"(c[1]), "+f"(c[2]), "+f"(c[3])
        : "r"(a[0]), "r"(a[1]), "r"(a[2]), "r"(a[3]), "r"(b[0]), "r"(b[1]));
}

__device__ __forceinline__ void split_bf16(float x, __nv_bfloat16* hi, __nv_bfloat16* lo)
{
    __nv_bfloat16 h = __float2bfloat16_rn(x);
    *hi = h;
    *lo = __float2bfloat16_rn(x - __bfloat162float(h));
}

__global__ __launch_bounds__(256, 2)
void gemm_mma(const float* __restrict__ A, const float* __restrict__ B,
              const float* __restrict__ bias, float* __restrict__ C,
              int M, int N, int K, int act)
{
    __shared__ __align__(16) __nv_bfloat16 As[2][128*ASTRIDE];
    __shared__ __align__(16) __nv_bfloat16 Bs[2][32*BSTRIDE];

    const int t    = threadIdx.x;
    const int lane = t & 31;
    const int warp = t >> 5;
    const int wm   = warp >> 1;
    const int wn   = warp & 1;
    const int bm   = blockIdx.y * 128;
    const int bn   = blockIdx.x * 128;

    float acc[2][8][4];
    for (int i = 0; i < 2; i++) {
        for (int j = 0; j < 8; j++) {
            for (int e = 0; e < 4; e++) {
                acc[i][j][e] = 0.0f;
            }
        }
    }

    const uint32_t aHi = (uint32_t)__cvta_generic_to_shared(&As[0][0]);
    const uint32_t aLo = (uint32_t)__cvta_generic_to_shared(&As[1][0]);
    const uint32_t bHi = (uint32_t)__cvta_generic_to_shared(&Bs[0][0]);
    const uint32_t bLo = (uint32_t)__cvta_generic_to_shared(&Bs[1][0]);

    const int lm = lane & 15;
    const int lq = lane >> 4;

    for (int k0 = 0; k0 < K; k0 += 32) {
        // load + split-convert A tile (128 rows x 32 k)
#pragma unroll
        for (int i = 0; i < 4; i++) {
            int f  = t + i*256;
            int r  = f >> 3;
            int kq = f & 7;
            float4 a4 = *(const float4*)(A + (size_t)(bm + r)*K + k0 + kq*4);
            BF16x4 hv, lv;
            split_bf16(a4.x, &hv.b[0], &lv.b[0]);
            split_bf16(a4.y, &hv.b[1], &lv.b[1]);
            split_bf16(a4.z, &hv.b[2], &lv.b[2]);
            split_bf16(a4.w, &hv.b[3], &lv.b[3]);
            *(uint2*)(&As[0][r*ASTRIDE + kq*4]) = hv.u;
            *(uint2*)(&As[1][r*ASTRIDE + kq*4]) = lv.u;
        }
        // load + split-convert B tile (32 k x 128 n)
#pragma unroll
        for (int i = 0; i < 4; i++) {
            int f  = t + i*256;
            int r  = f >> 5;
            int nq = f & 31;
            float4 b4 = *(const float4*)(B + (size_t)(k0 + r)*N + bn + nq*4);
            BF16x4 hv, lv;
            split_bf16(b4.x, &hv.b[0], &lv.b[0]);
            split_bf16(b4.y, &hv.b[1], &lv.b[1]);
            split_bf16(b4.z, &hv.b[2], &lv.b[2]);
            split_bf16(b4.w, &hv.b[3], &lv.b[3]);
            *(uint2*)(&Bs[0][r*BSTRIDE + nq*4]) = hv.u;
            *(uint2*)(&Bs[1][r*BSTRIDE + nq*4]) = lv.u;
        }
        __syncthreads();

#pragma unroll
        for (int ks = 0; ks < 32; ks += 16) {
            uint32_t ahf[2][4];
            uint32_t alf[2][4];
#pragma unroll
            for (int i = 0; i < 2; i++) {
                uint32_t off = (uint32_t)(((wm*32 + i*16 + lm)*ASTRIDE + ks + lq*8) * 2);
                ldsm4(ahf[i], aHi + off);
                ldsm4(alf[i], aLo + off);
            }
#pragma unroll
            for (int np = 0; np < 4; np++) {
                uint32_t bhf[4];
                uint32_t blf[4];
                uint32_t off = (uint32_t)(((ks + lm)*BSTRIDE + wn*64 + np*16 + lq*8) * 2);
                ldsm4t(bhf, bHi + off);
                ldsm4t(blf, bLo + off);
#pragma unroll
                for (int i = 0; i < 2; i++) {
#pragma unroll
                    for (int jj = 0; jj < 2; jj++) {
                        int j = np*2 + jj;
                        mma16816(acc[i][j], ahf[i], bhf + jj*2);
                        mma16816(acc[i][j], ahf[i], blf + jj*2);
                        mma16816(acc[i][j], alf[i], bhf + jj*2);
                    }
                }
            }
        }
        __syncthreads();
    }

    // epilogue: bias + optional exact GELU
    const int tr = lane >> 2;
    const int tc = (lane & 3) * 2;
#pragma unroll
    for (int i = 0; i < 2; i++) {
#pragma unroll
        for (int j = 0; j < 8; j++) {
#pragma unroll
            for (int hh = 0; hh < 2; hh++) {
                int gr = bm + wm*32 + i*16 + tr + hh*8;
                int gc = bn + wn*64 + j*8 + tc;
                float u0 = acc[i][j][hh*2 + 0] + bias[gc];
                float u1 = acc[i][j][hh*2 + 1] + bias[gc + 1];
                if (act == 1) {
                    u0 = 0.5f*u0*(1.0f + erff(u0*0.70710678118654752f));
                    u1 = 0.5f*u1*(1.0f + erff(u1*0.70710678118654752f));
                }
                float2 o;
                o.x = u0;
                o.y = u1;
                *(float2*)(C + (size_t)gr*N + gc) = o;
            }
        }
    }
}

// ---------------- attention scores: sc[z,q,k] = (q.k)/8 ; 64x64 tile / block ----------------
__global__ void attn_scores(const float* __restrict__ q, const float* __restrict__ k,
                            float* __restrict__ sc)
{
    __shared__ float Qs[64][65];
    __shared__ float Ks[64][65];
    int kt = blockIdx.x;
    int qt = blockIdx.y;
    int z  = blockIdx.z;
    int b  = z / Hh;
    int h  = z % Hh;
    const float* qb = q + ((size_t)b*Ss)*Dd + h*HD;
    const float* kb = k + ((size_t)b*Ss)*Dd + h*HD;
    int t = threadIdx.x;
#pragma unroll
    for (int i = 0; i < 16; i++) {
        int idx = t + i*256;
        int r = idx >> 6;
        int c = idx & 63;
        Qs[r][c] = qb[(size_t)(qt*64 + r)*Dd + c];
        Ks[r][c] = kb[(size_t)(kt*64 + r)*Dd + c];
    }
    __syncthreads();
    int tx = t & 15;
    int ty = t >> 4;
    float acc[4][4];
    for (int i = 0; i < 4; i++) {
        for (int j = 0; j < 4; j++) {
            acc[i][j] = 0.0f;
        }
    }
#pragma unroll 4
    for (int kk = 0; kk < 64; kk++) {
        float av[4];
        float bv[4];
#pragma unroll
        for (int i = 0; i < 4; i++) {
            av[i] = Qs[ty*4 + i][kk];
            bv[i] = Ks[tx*4 + i][kk];
        }
#pragma unroll
        for (int i = 0; i < 4; i++) {
#pragma unroll
            for (int j = 0; j < 4; j++) {
                acc[i][j] = fmaf(av[i], bv[j], acc[i][j]);
            }
        }
    }
    float* outp = sc + (size_t)z*Ss*Ss;
#pragma unroll
    for (int i = 0; i < 4; i++) {
        size_t row = (size_t)(qt*64 + ty*4 + i);
#pragma unroll
        for (int j = 0; j < 4; j++) {
            outp[row*Ss + kt*64 + tx*4 + j] = acc[i][j]*0.125f;
        }
    }
}

// ---------------- row softmax with key mask bias, 1 block / row ----------------
__global__ void softmax_kernel(float* __restrict__ sc, const int* __restrict__ mask)
{
    __shared__ float red[256];
    size_t row = blockIdx.x;
    int z = blockIdx.x >> 9;
    int b = z / Hh;
    float* rp = sc + row*Ss;
    int t = threadIdx.x;
    float v0 = rp[t]       + ((mask[b*Ss + t]       != 0) ? 0.0f : -1e9f);
    float v1 = rp[t + 256] + ((mask[b*Ss + t + 256] != 0) ? 0.0f : -1e9f);
    float m = fmaxf(v0, v1);
    red[t] = m;
    __syncthreads();
    for (int o = 128; o > 0; o >>= 1) {
        if (t < o) red[t] = fmaxf(red[t], red[t + o]);
        __syncthreads();
    }
    m = red[0];
    __syncthreads();
    float e0 = __expf(v0 - m);
    float e1 = __expf(v1 - m);
    red[t] = e0 + e1;
    __syncthreads();
    for (int o = 128; o > 0; o >>= 1) {
        if (t < o) red[t] += red[t + o];
        __syncthreads();
    }
    float inv = 1.0f / red[0];
    rp[t]       = e0*inv;
    rp[t + 256] = e1*inv;
}

// ---------------- ctx = A @ V per head: 32 q-rows x 64 cols / block ----------------
__global__ void attn_ctx(const float* __restrict__ sc, const float* __restrict__ v,
                         float* __restrict__ ctx)
{
    __shared__ float As2[32][65];
    __shared__ float Vs[64][64];
    int qt = blockIdx.x;
    int z  = blockIdx.y;
    int b  = z / Hh;
    int h  = z % Hh;
    const float* ap = sc + (size_t)z*Ss*Ss;
    const float* vb = v + ((size_t)b*Ss)*Dd + h*HD;
    int t  = threadIdx.x;
    int r  = t >> 3;
    int cg = t & 7;
    float acc[8];
    for (int j = 0; j < 8; j++) {
        acc[j] = 0.0f;
    }
    for (int k0 = 0; k0 < Ss; k0 += 64) {
#pragma unroll
        for (int i = 0; i < 8; i++) {
            int idx = t + i*256;
            int rr = idx >> 6;
            int cc = idx & 63;
            As2[rr][cc] = ap[(size_t)(qt*32 + rr)*Ss + k0 + cc];
        }
#pragma unroll
        for (int i = 0; i < 16; i++) {
            int idx = t + i*256;
            int rr = idx >> 6;
            int cc = idx & 63;
            Vs[rr][cc] = vb[(size_t)(k0 + rr)*Dd + cc];
        }
        __syncthreads();
#pragma unroll 8
        for (int kk = 0; kk < 64; kk++) {
            float a = As2[r][kk];
            const float4* vp = (const float4*)(&Vs[kk][cg*8]);
            float4 x0 = vp[0];
            float4 x1 = vp[1];
            acc[0] = fmaf(a, x0.x, acc[0]);
            acc[1] = fmaf(a, x0.y, acc[1]);
            acc[2] = fmaf(a, x0.z, acc[2]);
            acc[3] = fmaf(a, x0.w, acc[3]);
            acc[4] = fmaf(a, x1.x, acc[4]);
            acc[5] = fmaf(a, x1.y, acc[5]);
            acc[6] = fmaf(a, x1.z, acc[6]);
            acc[7] = fmaf(a, x1.w, acc[7]);
        }
        __syncthreads();
    }
    size_t orow = (size_t)b*Ss + qt*32 + r;
#pragma unroll
    for (int j = 0; j < 8; j++) {
        ctx[orow*Dd + h*HD + cg*8 + j] = acc[j];
    }
}

// ---------------- head: logits = relu(x[:,0] @ preW + preB) @ clsW + clsB ----------------
__global__ void head_kernel(const float* __restrict__ x, const float* __restrict__ preW,
                            const float* __restrict__ preB, const float* __restrict__ clsW,
                            const float* __restrict__ clsB, float* __restrict__ out)
{
    __shared__ float xr[Dd];
    __shared__ float pre[Dd];
    int b = blockIdx.x;
    int t = threadIdx.x;
    for (int d = t; d < Dd; d += 256) {
        xr[d] = x[((size_t)b*Ss)*Dd + d];
    }
    __syncthreads();
    for (int o = t; o < Dd; o += 256) {
        float a = preB[o];
        for (int kk = 0; kk < Dd; kk++) {
            a = fmaf(xr[kk], preW[(size_t)kk*Dd + o], a);
        }
        pre[o] = fmaxf(a, 0.0f);
    }
    __syncthreads();
    if (t < 3) {
        float a = clsB[t];
        for (int kk = 0; kk < Dd; kk++) {
            a = fmaf(pre[kk], clsW[kk*3 + t], a);
        }
        out[b*3 + t] = a;
    }
}

// ---------------- host launcher ----------------
extern "C" void kernel_launch(void* const* d_in, const int* in_sizes, int n_in,
                              void* d_out, int out_size)
{
    const int*   input_ids = (const int*)d_in[0];
    const int*   seg_ids   = (const int*)d_in[1];
    const int*   attn_mask = (const int*)d_in[2];
    const float* emb_table = (const float*)d_in[4];
    const float* pos_emb   = (const float*)d_in[5];
    const float* emb_ln_s  = (const float*)d_in[6];
    const float* emb_ln_b  = (const float*)d_in[7];
    const float* Wq   = (const float*)d_in[8];
    const float* bq   = (const float*)d_in[9];
    const float* Wk   = (const float*)d_in[10];
    const float* bk   = (const float*)d_in[11];
    const float* Wv   = (const float*)d_in[12];
    const float* bv   = (const float*)d_in[13];
    const float* Wo   = (const float*)d_in[14];
    const float* bo   = (const float*)d_in[15];
    const float* ln1s = (const float*)d_in[16];
    const float* ln1b = (const float*)d_in[17];
    const float* W1   = (const float*)d_in[18];
    const float* b1   = (const float*)d_in[19];
    const float* W2   = (const float*)d_in[20];
    const float* b2   = (const float*)d_in[21];
    const float* ln2s = (const float*)d_in[22];
    const float* ln2b = (const float*)d_in[23];
    const float* preW = (const float*)d_in[24];
    const float* preB = (const float*)d_in[25];
    const float* clsW = (const float*)d_in[26];
    const float* clsB = (const float*)d_in[27];
    float* logits = (float*)d_out;

    float* x;
    float* tmp;
    float* q;
    float* k;
    float* v;
    float* ctx;
    float* ff;
    float* sc;
    cudaGetSymbolAddress((void**)&x,   g_x);
    cudaGetSymbolAddress((void**)&tmp, g_tmp);
    cudaGetSymbolAddress((void**)&q,   g_q);
    cudaGetSymbolAddress((void**)&k,   g_k);
    cudaGetSymbolAddress((void**)&v,   g_v);
    cudaGetSymbolAddress((void**)&ctx, g_ctx);
    cudaGetSymbolAddress((void**)&ff,  g_ff);
    cudaGetSymbolAddress((void**)&sc,  g_sc);

    merge_kernel<<<dim3(Ss, Bb), 128>>>(input_ids, seg_ids, emb_table, pos_emb, tmp);
    ln_kernel<<<NROWS, 256>>>(tmp, nullptr, x, emb_ln_s, emb_ln_b);

    dim3 gP(Dd/128, NROWS/128);
    dim3 gF1(FF/128, NROWS/128);

    for (int l = 0; l < Ll; l++) {
        const float* wq = Wq + (size_t)l*Dd*Dd;
        const float* wk = Wk + (size_t)l*Dd*Dd;
        const float* wv = Wv + (size_t)l*Dd*Dd;
        const float* wo = Wo + (size_t)l*Dd*Dd;
        const float* w1 = W1 + (size_t)l*Dd*FF;
        const float* w2 = W2 + (size_t)l*FF*Dd;

        gemm_mma<<<gP, 256>>>(x, wq, bq + l*Dd, q, NROWS, Dd, Dd, 0);
        gemm_mma<<<gP, 256>>>(x, wk, bk + l*Dd, k, NROWS, Dd, Dd, 0);
        gemm_mma<<<gP, 256>>>(x, wv, bv + l*Dd, v, NROWS, Dd, Dd, 0);

        attn_scores<<<dim3(Ss/64, Ss/64, BH), 256>>>(q, k, sc);
        softmax_kernel<<<BH*Ss, 256>>>(sc, attn_mask);
        attn_ctx<<<dim3(Ss/32, BH), 256>>>(sc, v, ctx);

        gemm_mma<<<gP, 256>>>(ctx, wo, bo + l*Dd, tmp, NROWS, Dd, Dd, 0);
        ln_kernel<<<NROWS, 256>>>(x, tmp, x, ln1s + l*Dd, ln1b + l*Dd);

        gemm_mma<<<gF1, 256>>>(x, w1, b1 + l*FF, ff, NROWS, FF, Dd, 1);
        gemm_mma<<<gP, 256>>>(ff, w2, b2 + l*Dd, tmp, NROWS, Dd, FF, 0);
        ln_kernel<<<NROWS, 256>>>(x, tmp, x, ln2s + l*Dd, ln2b + l*Dd);
    }

    head_kernel<<<Bb, 256>>>(x, preW, preB, clsW, clsB, logits);
}

// round 9
// speedup vs baseline: 3.1902x; 1.7441x over previous
#include <cuda_runtime.h>
#include <cuda_bf16.h>
#include <cstdint>
#include <math.h>

// Problem dims
#define Bb 16
#define Ss 512
#define Dd 768
#define Hh 12
#define FF 3072
#define Ll 6
#define HD 64
#define BH (Bb*Hh)
#define NROWS (Bb*Ss)

// ---------------- scratch (device globals; no runtime allocation) ----------------
__device__ float g_x  [NROWS*Dd];
__device__ float g_tmp[NROWS*Dd];
__device__ float g_q  [NROWS*Dd];
__device__ float g_k  [NROWS*Dd];
__device__ float g_v  [NROWS*Dd];
__device__ float g_ctx[NROWS*Dd];
__device__ float g_ff [NROWS*FF];

// ---------------- embedding segment-merge + pos add ----------------
__global__ void merge_kernel(const int* __restrict__ ids, const int* __restrict__ seg,
                             const float* __restrict__ emb, const float* __restrict__ pos,
                             float* __restrict__ out)
{
    int s = blockIdx.x;
    int b = blockIdx.y;
    const int* sr = seg + b*Ss;
    int lo = 0;
    int hi = Ss;
    while (lo < hi) {
        int m = (lo + hi) >> 1;
        if (sr[m] < s) lo = m + 1; else hi = m;
    }
    int st = lo;
    lo = st;
    hi = Ss;
    while (lo < hi) {
        int m = (lo + hi) >> 1;
        if (sr[m] <= s) lo = m + 1; else hi = m;
    }
    int en = lo;
    const int* idr = ids + b*Ss;
    for (int d = threadIdx.x; d < Dd; d += blockDim.x) {
        float a;
        if (st == en) {
            a = emb[d];
        } else {
            a = 0.0f;
            for (int i = st; i < en; i++) {
                a += emb[(size_t)idr[i]*Dd + d];
            }
        }
        out[((size_t)b*Ss + s)*Dd + d] = a + pos[s*Dd + d];
    }
}

// ---------------- LayerNorm (optionally with residual), 1 block / row ----------------
__global__ void ln_kernel(const float* __restrict__ in, const float* __restrict__ res,
                          float* __restrict__ out, const float* __restrict__ gamma,
                          const float* __restrict__ beta)
{
    __shared__ float red[256];
    int row = blockIdx.x;
    const float* ip = in + (size_t)row*Dd;
    const float* rp = (res != nullptr) ? (res + (size_t)row*Dd) : nullptr;
    int t = threadIdx.x;
    float v0 = ip[t];
    float v1 = ip[t + 256];
    float v2 = ip[t + 512];
    if (rp != nullptr) {
        v0 += rp[t];
        v1 += rp[t + 256];
        v2 += rp[t + 512];
    }
    red[t] = v0 + v1 + v2;
    __syncthreads();
    for (int o = 128; o > 0; o >>= 1) {
        if (t < o) red[t] += red[t + o];
        __syncthreads();
    }
    float mean = red[0] * (1.0f / Dd);
    __syncthreads();
    float d0 = v0 - mean;
    float d1 = v1 - mean;
    float d2 = v2 - mean;
    red[t] = d0*d0 + d1*d1 + d2*d2;
    __syncthreads();
    for (int o = 128; o > 0; o >>= 1) {
        if (t < o) red[t] += red[t + o];
        __syncthreads();
    }
    float inv = rsqrtf(red[0] * (1.0f / Dd) + 1e-12f);
    out[(size_t)row*Dd + t]       = d0*inv*gamma[t]       + beta[t];
    out[(size_t)row*Dd + t + 256] = d1*inv*gamma[t + 256] + beta[t + 256];
    out[(size_t)row*Dd + t + 512] = d2*inv*gamma[t + 512] + beta[t + 512];
}

// ---------------- common MMA helpers (bf16x3 split precision) ----------------

#define ASTRIDE 40
#define BSTRIDE 136

union BF16x4 {
    __nv_bfloat16 b[4];
    uint2 u;
};

__device__ __forceinline__ void ldsm4(uint32_t* r, uint32_t addr)
{
    asm volatile("ldmatrix.sync.aligned.m8n8.x4.shared.b16 {%0,%1,%2,%3}, [%4];"
        : "=r"(r[0]), "=r"(r[1]), "=r"(r[2]), "=r"(r[3]) : "r"(addr));
}

__device__ __forceinline__ void ldsm4t(uint32_t* r, uint32_t addr)
{
    asm volatile("ldmatrix.sync.aligned.m8n8.x4.trans.shared.b16 {%0,%1,%2,%3}, [%4];"
        : "=r"(r[0]), "=r"(r[1]), "=r"(r[2]), "=r"(r[3]) : "r"(addr));
}

__device__ __forceinline__ void mma16816(float* c, const uint32_t* a, const uint32_t* b)
{
    asm volatile("mma.sync.aligned.m16n8k16.row.col.f32.bf16.bf16.f32 "
        "{%0,%1,%2,%3}, {%4,%5,%6,%7}, {%8,%9}, {%0,%1,%2,%3};"
        : "+f"(c[0]), "+f"(c[1]), "+f"(c[2]), "+f"(c[3])
        : "r"(a[0]), "r"(a[1]), "r"(a[2]), "r"(a[3]), "r"(b[0]), "r"(b[1]));
}

__device__ __forceinline__ void split_bf16(float x, __nv_bfloat16* hi, __nv_bfloat16* lo)
{
    __nv_bfloat16 h = __float2bfloat16_rn(x);
    *hi = h;
    *lo = __float2bfloat16_rn(x - __bfloat162float(h));
}

__device__ __forceinline__ void pack_split(float x, float y, uint32_t* hp, uint32_t* lp)
{
    __nv_bfloat16 hx = __float2bfloat16_rn(x);
    __nv_bfloat16 hy = __float2bfloat16_rn(y);
    __nv_bfloat16 lx = __float2bfloat16_rn(x - __bfloat162float(hx));
    __nv_bfloat16 ly = __float2bfloat16_rn(y - __bfloat162float(hy));
    uint32_t hu = ((uint32_t)__bfloat16_as_ushort(hy) << 16) | (uint32_t)__bfloat16_as_ushort(hx);
    uint32_t lu = ((uint32_t)__bfloat16_as_ushort(ly) << 16) | (uint32_t)__bfloat16_as_ushort(lx);
    *hp = hu;
    *lp = lu;
}

// ---------------- tensor-core GEMM with bf16x3 split precision ----------------
// C[M,N] = act(A[M,K] @ B[K,N] + bias).  Identical to the R8-validated kernel.
__global__ __launch_bounds__(256, 2)
void gemm_mma(const float* __restrict__ A, const float* __restrict__ B,
              const float* __restrict__ bias, float* __restrict__ C,
              int M, int N, int K, int act)
{
    __shared__ __align__(16) __nv_bfloat16 As[2][128*ASTRIDE];
    __shared__ __align__(16) __nv_bfloat16 Bs[2][32*BSTRIDE];

    const int t    = threadIdx.x;
    const int lane = t & 31;
    const int warp = t >> 5;
    const int wm   = warp >> 1;
    const int wn   = warp & 1;
    const int bm   = blockIdx.y * 128;
    const int bn   = blockIdx.x * 128;

    float acc[2][8][4];
    for (int i = 0; i < 2; i++) {
        for (int j = 0; j < 8; j++) {
            for (int e = 0; e < 4; e++) {
                acc[i][j][e] = 0.0f;
            }
        }
    }

    const uint32_t aHi = (uint32_t)__cvta_generic_to_shared(&As[0][0]);
    const uint32_t aLo = (uint32_t)__cvta_generic_to_shared(&As[1][0]);
    const uint32_t bHi = (uint32_t)__cvta_generic_to_shared(&Bs[0][0]);
    const uint32_t bLo = (uint32_t)__cvta_generic_to_shared(&Bs[1][0]);

    const int lm = lane & 15;
    const int lq = lane >> 4;

    for (int k0 = 0; k0 < K; k0 += 32) {
#pragma unroll
        for (int i = 0; i < 4; i++) {
            int f  = t + i*256;
            int r  = f >> 3;
            int kq = f & 7;
            float4 a4 = *(const float4*)(A + (size_t)(bm + r)*K + k0 + kq*4);
            BF16x4 hv, lv;
            split_bf16(a4.x, &hv.b[0], &lv.b[0]);
            split_bf16(a4.y, &hv.b[1], &lv.b[1]);
            split_bf16(a4.z, &hv.b[2], &lv.b[2]);
            split_bf16(a4.w, &hv.b[3], &lv.b[3]);
            *(uint2*)(&As[0][r*ASTRIDE + kq*4]) = hv.u;
            *(uint2*)(&As[1][r*ASTRIDE + kq*4]) = lv.u;
        }
#pragma unroll
        for (int i = 0; i < 4; i++) {
            int f  = t + i*256;
            int r  = f >> 5;
            int nq = f & 31;
            float4 b4 = *(const float4*)(B + (size_t)(k0 + r)*N + bn + nq*4);
            BF16x4 hv, lv;
            split_bf16(b4.x, &hv.b[0], &lv.b[0]);
            split_bf16(b4.y, &hv.b[1], &lv.b[1]);
            split_bf16(b4.z, &hv.b[2], &lv.b[2]);
            split_bf16(b4.w, &hv.b[3], &lv.b[3]);
            *(uint2*)(&Bs[0][r*BSTRIDE + nq*4]) = hv.u;
            *(uint2*)(&Bs[1][r*BSTRIDE + nq*4]) = lv.u;
        }
        __syncthreads();

#pragma unroll
        for (int ks = 0; ks < 32; ks += 16) {
            uint32_t ahf[2][4];
            uint32_t alf[2][4];
#pragma unroll
            for (int i = 0; i < 2; i++) {
                uint32_t off = (uint32_t)(((wm*32 + i*16 + lm)*ASTRIDE + ks + lq*8) * 2);
                ldsm4(ahf[i], aHi + off);
                ldsm4(alf[i], aLo + off);
            }
#pragma unroll
            for (int np = 0; np < 4; np++) {
                uint32_t bhf[4];
                uint32_t blf[4];
                uint32_t off = (uint32_t)(((ks + lm)*BSTRIDE + wn*64 + np*16 + lq*8) * 2);
                ldsm4t(bhf, bHi + off);
                ldsm4t(blf, bLo + off);
#pragma unroll
                for (int i = 0; i < 2; i++) {
#pragma unroll
                    for (int jj = 0; jj < 2; jj++) {
                        int j = np*2 + jj;
                        mma16816(acc[i][j], ahf[i], bhf + jj*2);
                        mma16816(acc[i][j], ahf[i], blf + jj*2);
                        mma16816(acc[i][j], alf[i], bhf + jj*2);
                    }
                }
            }
        }
        __syncthreads();
    }

    const int tr = lane >> 2;
    const int tc = (lane & 3) * 2;
#pragma unroll
    for (int i = 0; i < 2; i++) {
#pragma unroll
        for (int j = 0; j < 8; j++) {
#pragma unroll
            for (int hh = 0; hh < 2; hh++) {
                int gr = bm + wm*32 + i*16 + tr + hh*8;
                int gc = bn + wn*64 + j*8 + tc;
                float u0 = acc[i][j][hh*2 + 0] + bias[gc];
                float u1 = acc[i][j][hh*2 + 1] + bias[gc + 1];
                if (act == 1) {
                    u0 = 0.5f*u0*(1.0f + erff(u0*0.70710678118654752f));
                    u1 = 0.5f*u1*(1.0f + erff(u1*0.70710678118654752f));
                }
                float2 o;
                o.x = u0;
                o.y = u1;
                *(float2*)(C + (size_t)gr*N + gc) = o;
            }
        }
    }
}

// ---------------- fused flash attention (bf16x3 split MMA, online softmax) ----------------
// Block = 128 q rows of one (b,h). 8 warps, each owns m16 of q.
// Q kept in register fragments; loop over 8 key tiles of 64.
// S = Q K^T / 8 + mask; online softmax per warp (quad shuffles); O += P V.

#define QS 72   // smem row stride in bf16 elements (144B rows -> ldmatrix conflict-free)

__global__ __launch_bounds__(256, 1)
void flash_attn(const float* __restrict__ qg, const float* __restrict__ kg,
                const float* __restrict__ vg, const int* __restrict__ mask,
                float* __restrict__ ctx)
{
    __shared__ __align__(16) __nv_bfloat16 sm[256*QS];   // 36,864 B, aliased across phases
    __shared__ float smask[64];

    const int t    = threadIdx.x;
    const int lane = t & 31;
    const int w    = t >> 5;
    const int qt   = blockIdx.x;     // q tile (0..3)
    const int z    = blockIdx.y;     // (b,h)
    const int b    = z / Hh;
    const int h    = z % Hh;

    const int lm = lane & 15;
    const int lq = lane >> 4;
    const int tr = lane >> 2;
    const int tc = (lane & 3) * 2;

    __nv_bfloat16* Qh = sm;             // phase 1: [128][QS]
    __nv_bfloat16* Ql = sm + 128*QS;
    __nv_bfloat16* Kh = sm;             // phase 2: [64][QS] each
    __nv_bfloat16* Kl = sm + 64*QS;
    __nv_bfloat16* Vh = sm + 128*QS;
    __nv_bfloat16* Vl = sm + 192*QS;

    // ---- phase 1: load Q tile (128 x 64), split to bf16 hi/lo ----
    {
        const float* qp = qg + ((size_t)(b*Ss + qt*128))*Dd + h*HD;
#pragma unroll
        for (int i = 0; i < 8; i++) {
            int f  = t + i*256;
            int r  = f >> 4;
            int c4 = f & 15;
            float4 a4 = *(const float4*)(qp + (size_t)r*Dd + c4*4);
            BF16x4 hv, lv;
            split_bf16(a4.x, &hv.b[0], &lv.b[0]);
            split_bf16(a4.y, &hv.b[1], &lv.b[1]);
            split_bf16(a4.z, &hv.b[2], &lv.b[2]);
            split_bf16(a4.w, &hv.b[3], &lv.b[3]);
            *(uint2*)(Qh + r*QS + c4*4) = hv.u;
            *(uint2*)(Ql + r*QS + c4*4) = lv.u;
        }
    }
    __syncthreads();

    // per-warp Q fragments: 4 hd k16-tiles
    uint32_t qh[4][4];
    uint32_t ql[4][4];
    {
        uint32_t qbh = (uint32_t)__cvta_generic_to_shared(Qh);
        uint32_t qbl = (uint32_t)__cvta_generic_to_shared(Ql);
#pragma unroll
        for (int kt = 0; kt < 4; kt++) {
            uint32_t off = (uint32_t)(((w*16 + lm)*QS + kt*16 + lq*8) * 2);
            ldsm4(qh[kt], qbh + off);
            ldsm4(ql[kt], qbl + off);
        }
    }
    __syncthreads();   // Q smem may now be overwritten by K/V

    float o[8][4];
#pragma unroll
    for (int j = 0; j < 8; j++) {
        o[j][0] = 0.0f; o[j][1] = 0.0f; o[j][2] = 0.0f; o[j][3] = 0.0f;
    }
    float m0 = -1e30f;
    float m1 = -1e30f;
    float l0 = 0.0f;
    float l1 = 0.0f;

    const uint32_t kbh = (uint32_t)__cvta_generic_to_shared(Kh);
    const uint32_t kbl = (uint32_t)__cvta_generic_to_shared(Kl);
    const uint32_t vbh = (uint32_t)__cvta_generic_to_shared(Vh);
    const uint32_t vbl = (uint32_t)__cvta_generic_to_shared(Vl);

    for (int kt8 = 0; kt8 < 8; kt8++) {
        // ---- load K/V tiles (64 x 64), split ----
        {
            const float* kp = kg + ((size_t)(b*Ss + kt8*64))*Dd + h*HD;
            const float* vp = vg + ((size_t)(b*Ss + kt8*64))*Dd + h*HD;
#pragma unroll
            for (int i = 0; i < 4; i++) {
                int f  = t + i*256;
                int r  = f >> 4;
                int c4 = f & 15;
                float4 a4 = *(const float4*)(kp + (size_t)r*Dd + c4*4);
                BF16x4 hv, lv;
                split_bf16(a4.x, &hv.b[0], &lv.b[0]);
                split_bf16(a4.y, &hv.b[1], &lv.b[1]);
                split_bf16(a4.z, &hv.b[2], &lv.b[2]);
                split_bf16(a4.w, &hv.b[3], &lv.b[3]);
                *(uint2*)(Kh + r*QS + c4*4) = hv.u;
                *(uint2*)(Kl + r*QS + c4*4) = lv.u;
                float4 b4 = *(const float4*)(vp + (size_t)r*Dd + c4*4);
                split_bf16(b4.x, &hv.b[0], &lv.b[0]);
                split_bf16(b4.y, &hv.b[1], &lv.b[1]);
                split_bf16(b4.z, &hv.b[2], &lv.b[2]);
                split_bf16(b4.w, &hv.b[3], &lv.b[3]);
                *(uint2*)(Vh + r*QS + c4*4) = hv.u;
                *(uint2*)(Vl + r*QS + c4*4) = lv.u;
            }
        }
        if (t < 64) {
            smask[t] = (mask[b*Ss + kt8*64 + t] != 0) ? 0.0f : -1e9f;
        }
        __syncthreads();

        // ---- S = Q K^T (split bf16x3), per warp m16 x n64 ----
        float s[8][4];
#pragma unroll
        for (int j = 0; j < 8; j++) {
            s[j][0] = 0.0f; s[j][1] = 0.0f; s[j][2] = 0.0f; s[j][3] = 0.0f;
        }
#pragma unroll
        for (int kt = 0; kt < 4; kt++) {
#pragma unroll
            for (int nt = 0; nt < 4; nt++) {
                uint32_t off = (uint32_t)(((nt*16 + lm)*QS + kt*16 + lq*8) * 2);
                uint32_t khf[4];
                uint32_t klf[4];
                ldsm4(khf, kbh + off);
                ldsm4(klf, kbl + off);
                // K stored [key][hd]: non-trans ldsm tile remap -> b pairs {0,2} and {1,3}
                uint32_t b0h[2] = {khf[0], khf[2]};
                uint32_t b1h[2] = {khf[1], khf[3]};
                uint32_t b0l[2] = {klf[0], klf[2]};
                uint32_t b1l[2] = {klf[1], klf[3]};
                mma16816(s[nt*2],     qh[kt], b0h);
                mma16816(s[nt*2],     qh[kt], b0l);
                mma16816(s[nt*2],     ql[kt], b0h);
                mma16816(s[nt*2 + 1], qh[kt], b1h);
                mma16816(s[nt*2 + 1], qh[kt], b1l);
                mma16816(s[nt*2 + 1], ql[kt], b1h);
            }
        }

        // ---- scale + mask + online softmax (rows tr and tr+8 of warp m16) ----
        float mx0 = -1e30f;
        float mx1 = -1e30f;
#pragma unroll
        for (int j = 0; j < 8; j++) {
            float bi0 = smask[j*8 + tc];
            float bi1 = smask[j*8 + tc + 1];
            s[j][0] = s[j][0]*0.125f + bi0;
            s[j][1] = s[j][1]*0.125f + bi1;
            s[j][2] = s[j][2]*0.125f + bi0;
            s[j][3] = s[j][3]*0.125f + bi1;
            mx0 = fmaxf(mx0, fmaxf(s[j][0], s[j][1]));
            mx1 = fmaxf(mx1, fmaxf(s[j][2], s[j][3]));
        }
        mx0 = fmaxf(mx0, __shfl_xor_sync(0xffffffffu, mx0, 1));
        mx0 = fmaxf(mx0, __shfl_xor_sync(0xffffffffu, mx0, 2));
        mx1 = fmaxf(mx1, __shfl_xor_sync(0xffffffffu, mx1, 1));
        mx1 = fmaxf(mx1, __shfl_xor_sync(0xffffffffu, mx1, 2));
        float mn0 = fmaxf(m0, mx0);
        float mn1 = fmaxf(m1, mx1);
        float sc0 = __expf(m0 - mn0);
        float sc1 = __expf(m1 - mn1);
        m0 = mn0;
        m1 = mn1;
        float su0 = 0.0f;
        float su1 = 0.0f;
#pragma unroll
        for (int j = 0; j < 8; j++) {
            s[j][0] = __expf(s[j][0] - mn0);
            s[j][1] = __expf(s[j][1] - mn0);
            s[j][2] = __expf(s[j][2] - mn1);
            s[j][3] = __expf(s[j][3] - mn1);
            su0 += s[j][0] + s[j][1];
            su1 += s[j][2] + s[j][3];
            o[j][0] *= sc0;
            o[j][1] *= sc0;
            o[j][2] *= sc1;
            o[j][3] *= sc1;
        }
        su0 += __shfl_xor_sync(0xffffffffu, su0, 1);
        su0 += __shfl_xor_sync(0xffffffffu, su0, 2);
        su1 += __shfl_xor_sync(0xffffffffu, su1, 1);
        su1 += __shfl_xor_sync(0xffffffffu, su1, 2);
        l0 = l0*sc0 + su0;
        l1 = l1*sc1 + su1;

        // ---- O += P V (P rebuilt from S c-frags; split bf16x3) ----
#pragma unroll
        for (int kt = 0; kt < 4; kt++) {
            uint32_t ph[4];
            uint32_t pl[4];
            pack_split(s[kt*2][0],     s[kt*2][1],     &ph[0], &pl[0]);
            pack_split(s[kt*2][2],     s[kt*2][3],     &ph[1], &pl[1]);
            pack_split(s[kt*2 + 1][0], s[kt*2 + 1][1], &ph[2], &pl[2]);
            pack_split(s[kt*2 + 1][2], s[kt*2 + 1][3], &ph[3], &pl[3]);
#pragma unroll
            for (int nt = 0; nt < 4; nt++) {
                uint32_t off = (uint32_t)(((kt*16 + lm)*QS + nt*16 + lq*8) * 2);
                uint32_t vhf[4];
                uint32_t vlf[4];
                ldsm4t(vhf, vbh + off);
                ldsm4t(vlf, vbl + off);
                mma16816(o[nt*2],     ph, vhf);
                mma16816(o[nt*2],     ph, vlf);
                mma16816(o[nt*2],     pl, vhf);
                mma16816(o[nt*2 + 1], ph, vhf + 2);
                mma16816(o[nt*2 + 1], ph, vlf + 2);
                mma16816(o[nt*2 + 1], pl, vhf + 2);
            }
        }
        __syncthreads();   // before next tile overwrites K/V
    }

    // ---- normalize and write ctx ----
    float inv0 = 1.0f / l0;
    float inv1 = 1.0f / l1;
    int gr0 = qt*128 + w*16 + tr;
#pragma unroll
    for (int j = 0; j < 8; j++) {
        int gc = h*HD + j*8 + tc;
        float2 o0;
        o0.x = o[j][0]*inv0;
        o0.y = o[j][1]*inv0;
        float2 o1;
        o1.x = o[j][2]*inv1;
        o1.y = o[j][3]*inv1;
        *(float2*)(ctx + ((size_t)(b*Ss) + gr0)*Dd + gc)     = o0;
        *(float2*)(ctx + ((size_t)(b*Ss) + gr0 + 8)*Dd + gc) = o1;
    }
}

// ---------------- head: logits = relu(x[:,0] @ preW + preB) @ clsW + clsB ----------------
__global__ void head_kernel(const float* __restrict__ x, const float* __restrict__ preW,
                            const float* __restrict__ preB, const float* __restrict__ clsW,
                            const float* __restrict__ clsB, float* __restrict__ out)
{
    __shared__ float xr[Dd];
    __shared__ float pre[Dd];
    int b = blockIdx.x;
    int t = threadIdx.x;
    for (int d = t; d < Dd; d += 256) {
        xr[d] = x[((size_t)b*Ss)*Dd + d];
    }
    __syncthreads();
    for (int o = t; o < Dd; o += 256) {
        float a = preB[o];
        for (int kk = 0; kk < Dd; kk++) {
            a = fmaf(xr[kk], preW[(size_t)kk*Dd + o], a);
        }
        pre[o] = fmaxf(a, 0.0f);
    }
    __syncthreads();
    if (t < 3) {
        float a = clsB[t];
        for (int kk = 0; kk < Dd; kk++) {
            a = fmaf(pre[kk], clsW[kk*3 + t], a);
        }
        out[b*3 + t] = a;
    }
}

// ---------------- host launcher ----------------
extern "C" void kernel_launch(void* const* d_in, const int* in_sizes, int n_in,
                              void* d_out, int out_size)
{
    const int*   input_ids = (const int*)d_in[0];
    const int*   seg_ids   = (const int*)d_in[1];
    const int*   attn_mask = (const int*)d_in[2];
    const float* emb_table = (const float*)d_in[4];
    const float* pos_emb   = (const float*)d_in[5];
    const float* emb_ln_s  = (const float*)d_in[6];
    const float* emb_ln_b  = (const float*)d_in[7];
    const float* Wq   = (const float*)d_in[8];
    const float* bq   = (const float*)d_in[9];
    const float* Wk   = (const float*)d_in[10];
    const float* bk   = (const float*)d_in[11];
    const float* Wv   = (const float*)d_in[12];
    const float* bv   = (const float*)d_in[13];
    const float* Wo   = (const float*)d_in[14];
    const float* bo   = (const float*)d_in[15];
    const float* ln1s = (const float*)d_in[16];
    const float* ln1b = (const float*)d_in[17];
    const float* W1   = (const float*)d_in[18];
    const float* b1   = (const float*)d_in[19];
    const float* W2   = (const float*)d_in[20];
    const float* b2   = (const float*)d_in[21];
    const float* ln2s = (const float*)d_in[22];
    const float* ln2b = (const float*)d_in[23];
    const float* preW = (const float*)d_in[24];
    const float* preB = (const float*)d_in[25];
    const float* clsW = (const float*)d_in[26];
    const float* clsB = (const float*)d_in[27];
    float* logits = (float*)d_out;

    float* x;
    float* tmp;
    float* q;
    float* k;
    float* v;
    float* ctx;
    float* ff;
    cudaGetSymbolAddress((void**)&x,   g_x);
    cudaGetSymbolAddress((void**)&tmp, g_tmp);
    cudaGetSymbolAddress((void**)&q,   g_q);
    cudaGetSymbolAddress((void**)&k,   g_k);
    cudaGetSymbolAddress((void**)&v,   g_v);
    cudaGetSymbolAddress((void**)&ctx, g_ctx);
    cudaGetSymbolAddress((void**)&ff,  g_ff);

    merge_kernel<<<dim3(Ss, Bb), 128>>>(input_ids, seg_ids, emb_table, pos_emb, tmp);
    ln_kernel<<<NROWS, 256>>>(tmp, nullptr, x, emb_ln_s, emb_ln_b);

    dim3 gP(Dd/128, NROWS/128);
    dim3 gF1(FF/128, NROWS/128);

    for (int l = 0; l < Ll; l++) {
        const float* wq = Wq + (size_t)l*Dd*Dd;
        const float* wk = Wk + (size_t)l*Dd*Dd;
        const float* wv = Wv + (size_t)l*Dd*Dd;
        const float* wo = Wo + (size_t)l*Dd*Dd;
        const float* w1 = W1 + (size_t)l*Dd*FF;
        const float* w2 = W2 + (size_t)l*FF*Dd;

        gemm_mma<<<gP, 256>>>(x, wq, bq + l*Dd, q, NROWS, Dd, Dd, 0);
        gemm_mma<<<gP, 256>>>(x, wk, bk + l*Dd, k, NROWS, Dd, Dd, 0);
        gemm_mma<<<gP, 256>>>(x, wv, bv + l*Dd, v, NROWS, Dd, Dd, 0);

        flash_attn<<<dim3(Ss/128, BH), 256>>>(q, k, v, attn_mask, ctx);

        gemm_mma<<<gP, 256>>>(ctx, wo, bo + l*Dd, tmp, NROWS, Dd, Dd, 0);
        ln_kernel<<<NROWS, 256>>>(x, tmp, x, ln1s + l*Dd, ln1b + l*Dd);

        gemm_mma<<<gF1, 256>>>(x, w1, b1 + l*FF, ff, NROWS, FF, Dd, 1);
        gemm_mma<<<gP, 256>>>(ff, w2, b2 + l*Dd, tmp, NROWS, Dd, FF, 0);
        ln_kernel<<<NROWS, 256>>>(x, tmp, x, ln2s + l*Dd, ln2b + l*Dd);
    }

    head_kernel<<<Bb, 256>>>(x, preW, preB, clsW, clsB, logits);
}

// round 12
// speedup vs baseline: 3.4780x; 1.0902x over previous
#include <cuda_runtime.h>
#include <cuda_bf16.h>
#include <cstdint>
#include <math.h>

// Problem dims
#define Bb 16
#define Ss 512
#define Dd 768
#define Hh 12
#define FF 3072
#define Ll 6
#define HD 64
#define BH (Bb*Hh)
#define NROWS (Bb*Ss)

#define SZP (Ll*Dd*Dd)
#define SZF (Ll*Dd*FF)
#define WTOT (4*SZP + 2*SZF)

// ---------------- scratch (device globals; no runtime allocation) ----------------
__device__ float g_x  [NROWS*Dd];
__device__ float g_tmp[NROWS*Dd];
__device__ float g_q  [NROWS*Dd];
__device__ float g_k  [NROWS*Dd];
__device__ float g_v  [NROWS*Dd];

__device__ __nv_bfloat16 g_wh[WTOT];
__device__ __nv_bfloat16 g_wl[WTOT];
__device__ __nv_bfloat16 g_xh[NROWS*Dd];
__device__ __nv_bfloat16 g_xl[NROWS*Dd];
__device__ __nv_bfloat16 g_ch[NROWS*Dd];
__device__ __nv_bfloat16 g_cl[NROWS*Dd];
__device__ __nv_bfloat16 g_fh[NROWS*FF];
__device__ __nv_bfloat16 g_fl[NROWS*FF];

// ---------------- common helpers ----------------
union BF16x4 {
    __nv_bfloat16 b[4];
    uint2 u;
};

__device__ __forceinline__ void ldsm4(uint32_t* r, uint32_t addr)
{
    asm volatile("ldmatrix.sync.aligned.m8n8.x4.shared.b16 {%0,%1,%2,%3}, [%4];"
        : "=r"(r[0]), "=r"(r[1]), "=r"(r[2]), "=r"(r[3]) : "r"(addr));
}

__device__ __forceinline__ void ldsm4t(uint32_t* r, uint32_t addr)
{
    asm volatile("ldmatrix.sync.aligned.m8n8.x4.trans.shared.b16 {%0,%1,%2,%3}, [%4];"
        : "=r"(r[0]), "=r"(r[1]), "=r"(r[2]), "=r"(r[3]) : "r"(addr));
}

__device__ __forceinline__ void mma16816(float* c, const uint32_t* a, const uint32_t* b)
{
    asm volatile("mma.sync.aligned.m16n8k16.row.col.f32.bf16.bf16.f32 "
        "{%0,%1,%2,%3}, {%4,%5,%6,%7}, {%8,%9}, {%0,%1,%2,%3};"
        : "+f"(c[0]), "+f"(c[1]), "+f"(c[2]), "+f"(c[3])
        : "r"(a[0]), "r"(a[1]), "r"(a[2]), "r"(a[3]), "r"(b[0]), "r"(b[1]));
}

__device__ __forceinline__ void split_bf16(float x, __nv_bfloat16* hi, __nv_bfloat16* lo)
{
    __nv_bfloat16 h = __float2bfloat16_rn(x);
    *hi = h;
    *lo = __float2bfloat16_rn(x - __bfloat162float(h));
}

__device__ __forceinline__ void pack_split(float x, float y, uint32_t* hp, uint32_t* lp)
{
    __nv_bfloat16 hx = __float2bfloat16_rn(x);
    __nv_bfloat16 hy = __float2bfloat16_rn(y);
    __nv_bfloat16 lx = __float2bfloat16_rn(x - __bfloat162float(hx));
    __nv_bfloat16 ly = __float2bfloat16_rn(y - __bfloat162float(hy));
    *hp = ((uint32_t)__bfloat16_as_ushort(hy) << 16) | (uint32_t)__bfloat16_as_ushort(hx);
    *lp = ((uint32_t)__bfloat16_as_ushort(ly) << 16) | (uint32_t)__bfloat16_as_ushort(lx);
}

// ---------------- split: fp32 -> bf16 hi/lo (elementwise, float4) ----------------
__global__ void split_kernel(const float* __restrict__ src, __nv_bfloat16* __restrict__ hi,
                             __nv_bfloat16* __restrict__ lo, int n4)
{
    int i = blockIdx.x*blockDim.x + threadIdx.x;
    if (i < n4) {
        float4 v = ((const float4*)src)[i];
        BF16x4 h, l;
        split_bf16(v.x, &h.b[0], &l.b[0]);
        split_bf16(v.y, &h.b[1], &l.b[1]);
        split_bf16(v.z, &h.b[2], &l.b[2]);
        split_bf16(v.w, &h.b[3], &l.b[3]);
        ((uint2*)hi)[i] = h.u;
        ((uint2*)lo)[i] = l.u;
    }
}

// ---------------- embedding segment-merge + pos add ----------------
__global__ void merge_kernel(const int* __restrict__ ids, const int* __restrict__ seg,
                             const float* __restrict__ emb, const float* __restrict__ pos,
                             float* __restrict__ out)
{
    int s = blockIdx.x;
    int b = blockIdx.y;
    const int* sr = seg + b*Ss;
    int lo = 0;
    int hi = Ss;
    while (lo < hi) {
        int m = (lo + hi) >> 1;
        if (sr[m] < s) lo = m + 1; else hi = m;
    }
    int st = lo;
    lo = st;
    hi = Ss;
    while (lo < hi) {
        int m = (lo + hi) >> 1;
        if (sr[m] <= s) lo = m + 1; else hi = m;
    }
    int en = lo;
    const int* idr = ids + b*Ss;
    for (int d = threadIdx.x; d < Dd; d += blockDim.x) {
        float a;
        if (st == en) {
            a = emb[d];
        } else {
            a = 0.0f;
            for (int i = st; i < en; i++) {
                a += emb[(size_t)idr[i]*Dd + d];
            }
        }
        out[((size_t)b*Ss + s)*Dd + d] = a + pos[s*Dd + d];
    }
}

// ---------------- LayerNorm (+residual) -> fp32 out and split bf16 out ----------------
__global__ void ln_kernel(const float* __restrict__ in, const float* __restrict__ res,
                          float* __restrict__ out,
                          __nv_bfloat16* __restrict__ outh, __nv_bfloat16* __restrict__ outl,
                          const float* __restrict__ gamma, const float* __restrict__ beta)
{
    __shared__ float red[256];
    int row = blockIdx.x;
    const float* ip = in + (size_t)row*Dd;
    const float* rp = (res != nullptr) ? (res + (size_t)row*Dd) : nullptr;
    int t = threadIdx.x;
    float v0 = ip[t];
    float v1 = ip[t + 256];
    float v2 = ip[t + 512];
    if (rp != nullptr) {
        v0 += rp[t];
        v1 += rp[t + 256];
        v2 += rp[t + 512];
    }
    red[t] = v0 + v1 + v2;
    __syncthreads();
    for (int o = 128; o > 0; o >>= 1) {
        if (t < o) red[t] += red[t + o];
        __syncthreads();
    }
    float mean = red[0] * (1.0f / Dd);
    __syncthreads();
    float d0 = v0 - mean;
    float d1 = v1 - mean;
    float d2 = v2 - mean;
    red[t] = d0*d0 + d1*d1 + d2*d2;
    __syncthreads();
    for (int o = 128; o > 0; o >>= 1) {
        if (t < o) red[t] += red[t + o];
        __syncthreads();
    }
    float inv = rsqrtf(red[0] * (1.0f / Dd) + 1e-12f);
    float r0 = d0*inv*gamma[t]       + beta[t];
    float r1 = d1*inv*gamma[t + 256] + beta[t + 256];
    float r2 = d2*inv*gamma[t + 512] + beta[t + 512];
    size_t base = (size_t)row*Dd;
    out[base + t]       = r0;
    out[base + t + 256] = r1;
    out[base + t + 512] = r2;
    __nv_bfloat16 h, l;
    split_bf16(r0, &h, &l);
    outh[base + t] = h;
    outl[base + t] = l;
    split_bf16(r1, &h, &l);
    outh[base + t + 256] = h;
    outl[base + t + 256] = l;
    split_bf16(r2, &h, &l);
    outh[base + t + 512] = h;
    outl[base + t + 512] = l;
}

// ---------------- bf16x3 GEMM on pre-split inputs (static smem, sync loads) ----------------
// C[M,N] = act(A @ B + bias); A=[M,K] split bf16 (Ah,Al), B=[K,N] split bf16 (Bh,Bl).
// acc = Ah*Bh + Ah*Bl + Al*Bh (fp32). 128x128 block tile, k-tile 32, 256 threads,
// 8 warps as 4m x 2n, warp tile 32x64. Same transport as the R8/R9-proven kernel.
// act==0: write fp32 C.  act==1: exact GELU, write split bf16 Ch/Cl.

#define ASTRIDE 40
#define BSTRIDE 136

__global__ __launch_bounds__(256, 2)
void gemm_bs(const __nv_bfloat16* __restrict__ Ah, const __nv_bfloat16* __restrict__ Al,
             const __nv_bfloat16* __restrict__ Bh, const __nv_bfloat16* __restrict__ Bl,
             const float* __restrict__ bias, float* __restrict__ C,
             __nv_bfloat16* __restrict__ Ch, __nv_bfloat16* __restrict__ Cl,
             int M, int N, int K, int act)
{
    __shared__ __align__(16) __nv_bfloat16 Ash[128*ASTRIDE];
    __shared__ __align__(16) __nv_bfloat16 Asl[128*ASTRIDE];
    __shared__ __align__(16) __nv_bfloat16 Bsh[32*BSTRIDE];
    __shared__ __align__(16) __nv_bfloat16 Bsl[32*BSTRIDE];

    const int t    = threadIdx.x;
    const int lane = t & 31;
    const int warp = t >> 5;
    const int wm   = warp >> 1;
    const int wn   = warp & 1;
    const int bm   = blockIdx.y * 128;
    const int bn   = blockIdx.x * 128;
    const int lm   = lane & 15;
    const int lqq  = lane >> 4;

    float acc[2][8][4];
    for (int i = 0; i < 2; i++) {
        for (int j = 0; j < 8; j++) {
            for (int e = 0; e < 4; e++) {
                acc[i][j][e] = 0.0f;
            }
        }
    }

    const uint32_t aHi = (uint32_t)__cvta_generic_to_shared(Ash);
    const uint32_t aLo = (uint32_t)__cvta_generic_to_shared(Asl);
    const uint32_t bHi = (uint32_t)__cvta_generic_to_shared(Bsh);
    const uint32_t bLo = (uint32_t)__cvta_generic_to_shared(Bsl);

    for (int k0 = 0; k0 < K; k0 += 32) {
        // A tile: 128 rows x 32 k, hi and lo, 16B chunks (8 bf16)
#pragma unroll
        for (int i = 0; i < 2; i++) {
            int f  = t + i*256;
            int r  = f >> 2;
            int kc = f & 3;
            size_t go = (size_t)(bm + r)*K + k0 + kc*8;
            *(uint4*)(&Ash[r*ASTRIDE + kc*8]) = *(const uint4*)(Ah + go);
            *(uint4*)(&Asl[r*ASTRIDE + kc*8]) = *(const uint4*)(Al + go);
        }
        // B tile: 32 k-rows x 128 n, hi and lo
#pragma unroll
        for (int i = 0; i < 2; i++) {
            int f  = t + i*256;
            int r  = f >> 4;
            int nc = f & 15;
            size_t go = (size_t)(k0 + r)*N + bn + nc*8;
            *(uint4*)(&Bsh[r*BSTRIDE + nc*8]) = *(const uint4*)(Bh + go);
            *(uint4*)(&Bsl[r*BSTRIDE + nc*8]) = *(const uint4*)(Bl + go);
        }
        __syncthreads();

#pragma unroll
        for (int ks = 0; ks < 32; ks += 16) {
            uint32_t ahf[2][4];
            uint32_t alf[2][4];
#pragma unroll
            for (int i = 0; i < 2; i++) {
                uint32_t off = (uint32_t)(((wm*32 + i*16 + lm)*ASTRIDE + ks + lqq*8) * 2);
                ldsm4(ahf[i], aHi + off);
                ldsm4(alf[i], aLo + off);
            }
#pragma unroll
            for (int np = 0; np < 4; np++) {
                uint32_t bhf[4];
                uint32_t blf[4];
                uint32_t off = (uint32_t)(((ks + lm)*BSTRIDE + wn*64 + np*16 + lqq*8) * 2);
                ldsm4t(bhf, bHi + off);
                ldsm4t(blf, bLo + off);
#pragma unroll
                for (int i = 0; i < 2; i++) {
#pragma unroll
                    for (int jj = 0; jj < 2; jj++) {
                        int j = np*2 + jj;
                        mma16816(acc[i][j], ahf[i], bhf + jj*2);
                        mma16816(acc[i][j], ahf[i], blf + jj*2);
                        mma16816(acc[i][j], alf[i], bhf + jj*2);
                    }
                }
            }
        }
        __syncthreads();
    }

    const int tr = lane >> 2;
    const int tc = (lane & 3) * 2;
#pragma unroll
    for (int i = 0; i < 2; i++) {
#pragma unroll
        for (int j = 0; j < 8; j++) {
#pragma unroll
            for (int hh = 0; hh < 2; hh++) {
                int gr = bm + wm*32 + i*16 + tr + hh*8;
                int gc = bn + wn*64 + j*8 + tc;
                float u0 = acc[i][j][hh*2 + 0] + bias[gc];
                float u1 = acc[i][j][hh*2 + 1] + bias[gc + 1];
                if (act == 1) {
                    u0 = 0.5f*u0*(1.0f + erff(u0*0.70710678118654752f));
                    u1 = 0.5f*u1*(1.0f + erff(u1*0.70710678118654752f));
                    uint32_t hu, lu;
                    pack_split(u0, u1, &hu, &lu);
                    *(uint32_t*)(Ch + (size_t)gr*N + gc) = hu;
                    *(uint32_t*)(Cl + (size_t)gr*N + gc) = lu;
                } else {
                    float2 o2;
                    o2.x = u0;
                    o2.y = u1;
                    *(float2*)(C + (size_t)gr*N + gc) = o2;
                }
            }
        }
    }
}

// ---------------- fused flash attention (bf16x3 split MMA, online softmax) ----------------

#define QS 72

__global__ __launch_bounds__(256, 1)
void flash_attn(const float* __restrict__ qg, const float* __restrict__ kg,
                const float* __restrict__ vg, const int* __restrict__ mask,
                __nv_bfloat16* __restrict__ ctxh, __nv_bfloat16* __restrict__ ctxl)
{
    __shared__ __align__(16) __nv_bfloat16 sm[256*QS];
    __shared__ float smask[64];

    const int t    = threadIdx.x;
    const int lane = t & 31;
    const int w    = t >> 5;
    const int qt   = blockIdx.x;
    const int z    = blockIdx.y;
    const int b    = z / Hh;
    const int h    = z % Hh;

    const int lm = lane & 15;
    const int lq = lane >> 4;
    const int tr = lane >> 2;
    const int tc = (lane & 3) * 2;

    __nv_bfloat16* Qh = sm;
    __nv_bfloat16* Ql = sm + 128*QS;
    __nv_bfloat16* Kh = sm;
    __nv_bfloat16* Kl = sm + 64*QS;
    __nv_bfloat16* Vh = sm + 128*QS;
    __nv_bfloat16* Vl = sm + 192*QS;

    {
        const float* qp = qg + ((size_t)(b*Ss + qt*128))*Dd + h*HD;
#pragma unroll
        for (int i = 0; i < 8; i++) {
            int f  = t + i*256;
            int r  = f >> 4;
            int c4 = f & 15;
            float4 a4 = *(const float4*)(qp + (size_t)r*Dd + c4*4);
            BF16x4 hv, lv;
            split_bf16(a4.x, &hv.b[0], &lv.b[0]);
            split_bf16(a4.y, &hv.b[1], &lv.b[1]);
            split_bf16(a4.z, &hv.b[2], &lv.b[2]);
            split_bf16(a4.w, &hv.b[3], &lv.b[3]);
            *(uint2*)(Qh + r*QS + c4*4) = hv.u;
            *(uint2*)(Ql + r*QS + c4*4) = lv.u;
        }
    }
    __syncthreads();

    uint32_t qh[4][4];
    uint32_t ql[4][4];
    {
        uint32_t qbh = (uint32_t)__cvta_generic_to_shared(Qh);
        uint32_t qbl = (uint32_t)__cvta_generic_to_shared(Ql);
#pragma unroll
        for (int kt = 0; kt < 4; kt++) {
            uint32_t off = (uint32_t)(((w*16 + lm)*QS + kt*16 + lq*8) * 2);
            ldsm4(qh[kt], qbh + off);
            ldsm4(ql[kt], qbl + off);
        }
    }
    __syncthreads();

    float o[8][4];
#pragma unroll
    for (int j = 0; j < 8; j++) {
        o[j][0] = 0.0f; o[j][1] = 0.0f; o[j][2] = 0.0f; o[j][3] = 0.0f;
    }
    float m0 = -1e30f;
    float m1 = -1e30f;
    float l0 = 0.0f;
    float l1 = 0.0f;

    const uint32_t kbh = (uint32_t)__cvta_generic_to_shared(Kh);
    const uint32_t kbl = (uint32_t)__cvta_generic_to_shared(Kl);
    const uint32_t vbh = (uint32_t)__cvta_generic_to_shared(Vh);
    const uint32_t vbl = (uint32_t)__cvta_generic_to_shared(Vl);

    for (int kt8 = 0; kt8 < 8; kt8++) {
        {
            const float* kp = kg + ((size_t)(b*Ss + kt8*64))*Dd + h*HD;
            const float* vp = vg + ((size_t)(b*Ss + kt8*64))*Dd + h*HD;
#pragma unroll
            for (int i = 0; i < 4; i++) {
                int f  = t + i*256;
                int r  = f >> 4;
                int c4 = f & 15;
                float4 a4 = *(const float4*)(kp + (size_t)r*Dd + c4*4);
                BF16x4 hv, lv;
                split_bf16(a4.x, &hv.b[0], &lv.b[0]);
                split_bf16(a4.y, &hv.b[1], &lv.b[1]);
                split_bf16(a4.z, &hv.b[2], &lv.b[2]);
                split_bf16(a4.w, &hv.b[3], &lv.b[3]);
                *(uint2*)(Kh + r*QS + c4*4) = hv.u;
                *(uint2*)(Kl + r*QS + c4*4) = lv.u;
                float4 b4 = *(const float4*)(vp + (size_t)r*Dd + c4*4);
                split_bf16(b4.x, &hv.b[0], &lv.b[0]);
                split_bf16(b4.y, &hv.b[1], &lv.b[1]);
                split_bf16(b4.z, &hv.b[2], &lv.b[2]);
                split_bf16(b4.w, &hv.b[3], &lv.b[3]);
                *(uint2*)(Vh + r*QS + c4*4) = hv.u;
                *(uint2*)(Vl + r*QS + c4*4) = lv.u;
            }
        }
        if (t < 64) {
            smask[t] = (mask[b*Ss + kt8*64 + t] != 0) ? 0.0f : -1e9f;
        }
        __syncthreads();

        float s[8][4];
#pragma unroll
        for (int j = 0; j < 8; j++) {
            s[j][0] = 0.0f; s[j][1] = 0.0f; s[j][2] = 0.0f; s[j][3] = 0.0f;
        }
#pragma unroll
        for (int kt = 0; kt < 4; kt++) {
#pragma unroll
            for (int nt = 0; nt < 4; nt++) {
                uint32_t off = (uint32_t)(((nt*16 + lm)*QS + kt*16 + lq*8) * 2);
                uint32_t khf[4];
                uint32_t klf[4];
                ldsm4(khf, kbh + off);
                ldsm4(klf, kbl + off);
                uint32_t b0h[2] = {khf[0], khf[2]};
                uint32_t b1h[2] = {khf[1], khf[3]};
                uint32_t b0l[2] = {klf[0], klf[2]};
                uint32_t b1l[2] = {klf[1], klf[3]};
                mma16816(s[nt*2],     qh[kt], b0h);
                mma16816(s[nt*2],     qh[kt], b0l);
                mma16816(s[nt*2],     ql[kt], b0h);
                mma16816(s[nt*2 + 1], qh[kt], b1h);
                mma16816(s[nt*2 + 1], qh[kt], b1l);
                mma16816(s[nt*2 + 1], ql[kt], b1h);
            }
        }

        float mx0 = -1e30f;
        float mx1 = -1e30f;
#pragma unroll
        for (int j = 0; j < 8; j++) {
            float bi0 = smask[j*8 + tc];
            float bi1 = smask[j*8 + tc + 1];
            s[j][0] = s[j][0]*0.125f + bi0;
            s[j][1] = s[j][1]*0.125f + bi1;
            s[j][2] = s[j][2]*0.125f + bi0;
            s[j][3] = s[j][3]*0.125f + bi1;
            mx0 = fmaxf(mx0, fmaxf(s[j][0], s[j][1]));
            mx1 = fmaxf(mx1, fmaxf(s[j][2], s[j][3]));
        }
        mx0 = fmaxf(mx0, __shfl_xor_sync(0xffffffffu, mx0, 1));
        mx0 = fmaxf(mx0, __shfl_xor_sync(0xffffffffu, mx0, 2));
        mx1 = fmaxf(mx1, __shfl_xor_sync(0xffffffffu, mx1, 1));
        mx1 = fmaxf(mx1, __shfl_xor_sync(0xffffffffu, mx1, 2));
        float mn0 = fmaxf(m0, mx0);
        float mn1 = fmaxf(m1, mx1);
        float sc0 = __expf(m0 - mn0);
        float sc1 = __expf(m1 - mn1);
        m0 = mn0;
        m1 = mn1;
        float su0 = 0.0f;
        float su1 = 0.0f;
#pragma unroll
        for (int j = 0; j < 8; j++) {
            s[j][0] = __expf(s[j][0] - mn0);
            s[j][1] = __expf(s[j][1] - mn0);
            s[j][2] = __expf(s[j][2] - mn1);
            s[j][3] = __expf(s[j][3] - mn1);
            su0 += s[j][0] + s[j][1];
            su1 += s[j][2] + s[j][3];
            o[j][0] *= sc0;
            o[j][1] *= sc0;
            o[j][2] *= sc1;
            o[j][3] *= sc1;
        }
        su0 += __shfl_xor_sync(0xffffffffu, su0, 1);
        su0 += __shfl_xor_sync(0xffffffffu, su0, 2);
        su1 += __shfl_xor_sync(0xffffffffu, su1, 1);
        su1 += __shfl_xor_sync(0xffffffffu, su1, 2);
        l0 = l0*sc0 + su0;
        l1 = l1*sc1 + su1;

#pragma unroll
        for (int kt = 0; kt < 4; kt++) {
            uint32_t ph[4];
            uint32_t pl[4];
            pack_split(s[kt*2][0],     s[kt*2][1],     &ph[0], &pl[0]);
            pack_split(s[kt*2][2],     s[kt*2][3],     &ph[1], &pl[1]);
            pack_split(s[kt*2 + 1][0], s[kt*2 + 1][1], &ph[2], &pl[2]);
            pack_split(s[kt*2 + 1][2], s[kt*2 + 1][3], &ph[3], &pl[3]);
#pragma unroll
            for (int nt = 0; nt < 4; nt++) {
                uint32_t off = (uint32_t)(((kt*16 + lm)*QS + nt*16 + lq*8) * 2);
                uint32_t vhf[4];
                uint32_t vlf[4];
                ldsm4t(vhf, vbh + off);
                ldsm4t(vlf, vbl + off);
                mma16816(o[nt*2],     ph, vhf);
                mma16816(o[nt*2],     ph, vlf);
                mma16816(o[nt*2],     pl, vhf);
                mma16816(o[nt*2 + 1], ph, vhf + 2);
                mma16816(o[nt*2 + 1], ph, vlf + 2);
                mma16816(o[nt*2 + 1], pl, vhf + 2);
            }
        }
        __syncthreads();
    }

    float inv0 = 1.0f / l0;
    float inv1 = 1.0f / l1;
    int gr0 = qt*128 + w*16 + tr;
#pragma unroll
    for (int j = 0; j < 8; j++) {
        int gc = h*HD + j*8 + tc;
        size_t r0off = ((size_t)(b*Ss) + gr0)*Dd + gc;
        size_t r1off = ((size_t)(b*Ss) + gr0 + 8)*Dd + gc;
        uint32_t hu, lu;
        pack_split(o[j][0]*inv0, o[j][1]*inv0, &hu, &lu);
        *(uint32_t*)(ctxh + r0off) = hu;
        *(uint32_t*)(ctxl + r0off) = lu;
        pack_split(o[j][2]*inv1, o[j][3]*inv1, &hu, &lu);
        *(uint32_t*)(ctxh + r1off) = hu;
        *(uint32_t*)(ctxl + r1off) = lu;
    }
}

// ---------------- head: logits = relu(x[:,0] @ preW + preB) @ clsW + clsB ----------------
__global__ void head_kernel(const float* __restrict__ x, const float* __restrict__ preW,
                            const float* __restrict__ preB, const float* __restrict__ clsW,
                            const float* __restrict__ clsB, float* __restrict__ out)
{
    __shared__ float xr[Dd];
    __shared__ float pre[Dd];
    int b = blockIdx.x;
    int t = threadIdx.x;
    for (int d = t; d < Dd; d += 256) {
        xr[d] = x[((size_t)b*Ss)*Dd + d];
    }
    __syncthreads();
    for (int o = t; o < Dd; o += 256) {
        float a = preB[o];
        for (int kk = 0; kk < Dd; kk++) {
            a = fmaf(xr[kk], preW[(size_t)kk*Dd + o], a);
        }
        pre[o] = fmaxf(a, 0.0f);
    }
    __syncthreads();
    if (t < 3) {
        float a = clsB[t];
        for (int kk = 0; kk < Dd; kk++) {
            a = fmaf(pre[kk], clsW[kk*3 + t], a);
        }
        out[b*3 + t] = a;
    }
}

// ---------------- host launcher ----------------
extern "C" void kernel_launch(void* const* d_in, const int* in_sizes, int n_in,
                              void* d_out, int out_size)
{
    const int*   input_ids = (const int*)d_in[0];
    const int*   seg_ids   = (const int*)d_in[1];
    const int*   attn_mask = (const int*)d_in[2];
    const float* emb_table = (const float*)d_in[4];
    const float* pos_emb   = (const float*)d_in[5];
    const float* emb_ln_s  = (const float*)d_in[6];
    const float* emb_ln_b  = (const float*)d_in[7];
    const float* Wq   = (const float*)d_in[8];
    const float* bq   = (const float*)d_in[9];
    const float* Wk   = (const float*)d_in[10];
    const float* bk   = (const float*)d_in[11];
    const float* Wv   = (const float*)d_in[12];
    const float* bv   = (const float*)d_in[13];
    const float* Wo   = (const float*)d_in[14];
    const float* bo   = (const float*)d_in[15];
    const float* ln1s = (const float*)d_in[16];
    const float* ln1b = (const float*)d_in[17];
    const float* W1   = (const float*)d_in[18];
    const float* b1   = (const float*)d_in[19];
    const float* W2   = (const float*)d_in[20];
    const float* b2   = (const float*)d_in[21];
    const float* ln2s = (const float*)d_in[22];
    const float* ln2b = (const float*)d_in[23];
    const float* preW = (const float*)d_in[24];
    const float* preB = (const float*)d_in[25];
    const float* clsW = (const float*)d_in[26];
    const float* clsB = (const float*)d_in[27];
    float* logits = (float*)d_out;

    float* x;
    float* tmp;
    float* q;
    float* k;
    float* v;
    __nv_bfloat16* wh;
    __nv_bfloat16* wl;
    __nv_bfloat16* xh;
    __nv_bfloat16* xl;
    __nv_bfloat16* ch;
    __nv_bfloat16* cl;
    __nv_bfloat16* fh;
    __nv_bfloat16* fl;
    cudaGetSymbolAddress((void**)&x,   g_x);
    cudaGetSymbolAddress((void**)&tmp, g_tmp);
    cudaGetSymbolAddress((void**)&q,   g_q);
    cudaGetSymbolAddress((void**)&k,   g_k);
    cudaGetSymbolAddress((void**)&v,   g_v);
    cudaGetSymbolAddress((void**)&wh,  g_wh);
    cudaGetSymbolAddress((void**)&wl,  g_wl);
    cudaGetSymbolAddress((void**)&xh,  g_xh);
    cudaGetSymbolAddress((void**)&xl,  g_xl);
    cudaGetSymbolAddress((void**)&ch,  g_ch);
    cudaGetSymbolAddress((void**)&cl,  g_cl);
    cudaGetSymbolAddress((void**)&fh,  g_fh);
    cudaGetSymbolAddress((void**)&fl,  g_fl);

    {
        int n4p = SZP / 4;
        int n4f = SZF / 4;
        split_kernel<<<(n4p + 255)/256, 256>>>(Wq, wh + 0*(size_t)SZP, wl + 0*(size_t)SZP, n4p);
        split_kernel<<<(n4p + 255)/256, 256>>>(Wk, wh + 1*(size_t)SZP, wl + 1*(size_t)SZP, n4p);
        split_kernel<<<(n4p + 255)/256, 256>>>(Wv, wh + 2*(size_t)SZP, wl + 2*(size_t)SZP, n4p);
        split_kernel<<<(n4p + 255)/256, 256>>>(Wo, wh + 3*(size_t)SZP, wl + 3*(size_t)SZP, n4p);
        split_kernel<<<(n4f + 255)/256, 256>>>(W1, wh + 4*(size_t)SZP, wl + 4*(size_t)SZP, n4f);
        split_kernel<<<(n4f + 255)/256, 256>>>(W2, wh + 4*(size_t)SZP + SZF, wl + 4*(size_t)SZP + SZF, n4f);
    }

    merge_kernel<<<dim3(Ss, Bb), 128>>>(input_ids, seg_ids, emb_table, pos_emb, tmp);
    ln_kernel<<<NROWS, 256>>>(tmp, nullptr, x, xh, xl, emb_ln_s, emb_ln_b);

    dim3 gP(Dd/128, NROWS/128);
    dim3 gF1(FF/128, NROWS/128);

    for (int l = 0; l < Ll; l++) {
        const __nv_bfloat16* wqh = wh + 0*(size_t)SZP + (size_t)l*Dd*Dd;
        const __nv_bfloat16* wql = wl + 0*(size_t)SZP + (size_t)l*Dd*Dd;
        const __nv_bfloat16* wkh = wh + 1*(size_t)SZP + (size_t)l*Dd*Dd;
        const __nv_bfloat16* wkl = wl + 1*(size_t)SZP + (size_t)l*Dd*Dd;
        const __nv_bfloat16* wvh = wh + 2*(size_t)SZP + (size_t)l*Dd*Dd;
        const __nv_bfloat16* wvl = wl + 2*(size_t)SZP + (size_t)l*Dd*Dd;
        const __nv_bfloat16* woh = wh + 3*(size_t)SZP + (size_t)l*Dd*Dd;
        const __nv_bfloat16* wol = wl + 3*(size_t)SZP + (size_t)l*Dd*Dd;
        const __nv_bfloat16* w1h = wh + 4*(size_t)SZP + (size_t)l*Dd*FF;
        const __nv_bfloat16* w1l = wl + 4*(size_t)SZP + (size_t)l*Dd*FF;
        const __nv_bfloat16* w2h = wh + 4*(size_t)SZP + (size_t)SZF + (size_t)l*FF*Dd;
        const __nv_bfloat16* w2l = wl + 4*(size_t)SZP + (size_t)SZF + (size_t)l*FF*Dd;

        gemm_bs<<<gP, 256>>>(xh, xl, wqh, wql, bq + l*Dd, q, nullptr, nullptr, NROWS, Dd, Dd, 0);
        gemm_bs<<<gP, 256>>>(xh, xl, wkh, wkl, bk + l*Dd, k, nullptr, nullptr, NROWS, Dd, Dd, 0);
        gemm_bs<<<gP, 256>>>(xh, xl, wvh, wvl, bv + l*Dd, v, nullptr, nullptr, NROWS, Dd, Dd, 0);

        flash_attn<<<dim3(Ss/128, BH), 256>>>(q, k, v, attn_mask, ch, cl);

        gemm_bs<<<gP, 256>>>(ch, cl, woh, wol, bo + l*Dd, tmp, nullptr, nullptr, NROWS, Dd, Dd, 0);
        ln_kernel<<<NROWS, 256>>>(x, tmp, x, xh, xl, ln1s + l*Dd, ln1b + l*Dd);

        gemm_bs<<<gF1, 256>>>(xh, xl, w1h, w1l, b1 + l*FF, nullptr, fh, fl, NROWS, FF, Dd, 1);
        gemm_bs<<<gP, 256>>>(fh, fl, w2h, w2l, b2 + l*Dd, tmp, nullptr, nullptr, NROWS, Dd, FF, 0);
        ln_kernel<<<NROWS, 256>>>(x, tmp, x, xh, xl, ln2s + l*Dd, ln2b + l*Dd);
    }

    head_kernel<<<Bb, 256>>>(x, preW, preB, clsW, clsB, logits);
}